// round 1
// baseline (speedup 1.0000x reference)
#include <cuda_runtime.h>

// Problem constants
#define B_TOK 32768
#define DIM   256
#define E_NUM 8

// ---------------------------------------------------------------------------
// Routing scratch (device globals — no allocations allowed)
// ---------------------------------------------------------------------------
__device__ int   g_cnt[E_NUM];
__device__ int   g_ridx[E_NUM * B_TOK];
__device__ float g_rwt [E_NUM * B_TOK];

__global__ void zero_cnt_kernel() {
    if (threadIdx.x < E_NUM) g_cnt[threadIdx.x] = 0;
}

// ---------------------------------------------------------------------------
// Register-blocked 64x256 @ 256x256 fp32 GEMM tile.
// Block: 256 threads. warp id tc = token group (8 tokens), lane jc = col group
// (8 cols). Each thread accumulates an 8x8 sub-tile in registers.
// In: smem [64][256]. W: global (row-major [256][256]). Wt: smem staging
// [32][256]. Ends with __syncthreads() so the caller may overwrite In.
// ---------------------------------------------------------------------------
__device__ __forceinline__ void gemm_64x256(
    const float* __restrict__ In, const float4* __restrict__ W4g,
    float* __restrict__ Wt, float (&acc)[8][8], int tc, int jc, int tid)
{
    float4* Wt4 = (float4*)Wt;
#pragma unroll
    for (int a = 0; a < 8; a++)
#pragma unroll
        for (int b = 0; b < 8; b++) acc[a][b] = 0.f;

    for (int dt = 0; dt < 256; dt += 32) {
        __syncthreads();
#pragma unroll
        for (int i = 0; i < 8; i++)
            Wt4[tid + i * 256] = W4g[dt * 64 + tid + i * 256];
        __syncthreads();
#pragma unroll 1
        for (int dd = 0; dd < 32; dd += 4) {
            float4 xq[8];
#pragma unroll
            for (int tt = 0; tt < 8; tt++)
                xq[tt] = *(const float4*)&In[(tc * 8 + tt) * 256 + dt + dd];
#pragma unroll
            for (int q = 0; q < 4; q++) {
                float4 wa = Wt4[(dd + q) * 64 + jc * 2];
                float4 wb = Wt4[(dd + q) * 64 + jc * 2 + 1];
                float wv[8] = {wa.x, wa.y, wa.z, wa.w, wb.x, wb.y, wb.z, wb.w};
#pragma unroll
                for (int tt = 0; tt < 8; tt++) {
                    float xv = ((const float*)&xq[tt])[q];
#pragma unroll
                    for (int cc = 0; cc < 8; cc++)
                        acc[tt][cc] = fmaf(xv, wv[cc], acc[tt][cc]);
                }
            }
        }
    }
    __syncthreads();
}

// bias + LayerNorm + ReLU on the register tile, store to smem Out.
// Token rows are warp-private -> LN reduction is pure warp shuffles.
// bias/gma/bta pre-offset to expert (256 floats each).
__device__ __forceinline__ void bias_ln_relu_store(
    float (&acc)[8][8], const float* __restrict__ bias,
    const float* __restrict__ gma, const float* __restrict__ bta,
    float* __restrict__ Out, int tc, int jc)
{
    float bj[8], gj[8], ej[8];
#pragma unroll
    for (int cc = 0; cc < 8; cc++) {
        bj[cc] = bias[jc * 8 + cc];
        gj[cc] = gma[jc * 8 + cc];
        ej[cc] = bta[jc * 8 + cc];
    }
#pragma unroll
    for (int tt = 0; tt < 8; tt++) {
        float s = 0.f, s2 = 0.f;
#pragma unroll
        for (int cc = 0; cc < 8; cc++) {
            float v = acc[tt][cc] + bj[cc];
            acc[tt][cc] = v;
            s += v;
            s2 = fmaf(v, v, s2);
        }
#pragma unroll
        for (int o = 16; o > 0; o >>= 1) {
            s  += __shfl_xor_sync(0xffffffffu, s, o);
            s2 += __shfl_xor_sync(0xffffffffu, s2, o);
        }
        float m    = s * (1.f / 256.f);
        float var  = s2 * (1.f / 256.f) - m * m;
        float rstd = rsqrtf(var + 1e-5f);
        float ov[8];
#pragma unroll
        for (int cc = 0; cc < 8; cc++) {
            float v = (acc[tt][cc] - m) * rstd * gj[cc] + ej[cc];
            ov[cc] = fmaxf(v, 0.f);
        }
        float4* O4 = (float4*)&Out[(tc * 8 + tt) * 256 + jc * 8];
        O4[0] = make_float4(ov[0], ov[1], ov[2], ov[3]);
        O4[1] = make_float4(ov[4], ov[5], ov[6], ov[7]);
    }
}

// ---------------------------------------------------------------------------
// Gating: h = relu(x@gw1+gb1); logits = h@gw2+gb2; top-2 of softmax
// (renormalized -> softmax denominator cancels); routed list build.
// Block = 64 tokens, 256 threads. Dyn smem: A[64*256] + Wt[32*256].
// ---------------------------------------------------------------------------
#define GATE_SMEM ((64 * 256 + 32 * 256) * 4)

__global__ __launch_bounds__(256, 2) void gating_kernel(
    const float* __restrict__ x,
    const float* __restrict__ gw1, const float* __restrict__ gb1,
    const float* __restrict__ gw2, const float* __restrict__ gb2)
{
    extern __shared__ float sm[];
    float* A  = sm;              // 64 x 256
    float* Wt = sm + 64 * 256;   // 32 x 256
    __shared__ float lgs[64 * 8];
    __shared__ int scnt[E_NUM], sbase[E_NUM], soff[E_NUM];

    int tid = threadIdx.x;
    int tc = tid >> 5;
    int jc = tid & 31;

    // load x tile (contiguous rows)
    const float4* x4 = (const float4*)(x + (size_t)blockIdx.x * 64 * 256);
    float4* A4 = (float4*)A;
#pragma unroll
    for (int i = 0; i < 16; i++) A4[tid + i * 256] = x4[tid + i * 256];

    float acc[8][8];
    gemm_64x256(A, (const float4*)gw1, Wt, acc, tc, jc, tid);

    // bias + relu, write h back into A (gemm ended with syncthreads)
    {
        float bj[8];
#pragma unroll
        for (int cc = 0; cc < 8; cc++) bj[cc] = gb1[jc * 8 + cc];
#pragma unroll
        for (int tt = 0; tt < 8; tt++) {
            float ov[8];
#pragma unroll
            for (int cc = 0; cc < 8; cc++)
                ov[cc] = fmaxf(acc[tt][cc] + bj[cc], 0.f);
            float4* O4 = (float4*)&A[(tc * 8 + tt) * 256 + jc * 8];
            O4[0] = make_float4(ov[0], ov[1], ov[2], ov[3]);
            O4[1] = make_float4(ov[4], ov[5], ov[6], ov[7]);
        }
    }
    if (tid < E_NUM) { scnt[tid] = 0; soff[tid] = 0; }
    __syncthreads();

    // layer 2: 64 tokens x 8 experts = 512 outputs
    for (int idx = tid; idx < 512; idx += 256) {
        int t = idx >> 3, e = idx & 7;
        float s = gb2[e];
        for (int k = 0; k < 256; k++)
            s = fmaf(A[t * 256 + k], gw2[k * 8 + e], s);
        lgs[t * 8 + e] = s;
    }
    __syncthreads();

    // top-2 + block-aggregated routing
    int i0 = 0, i1 = 0;
    float w0f = 0.f, w1f = 0.f;
    int token = blockIdx.x * 64 + tid;
    if (tid < 64) {
        float l0 = -1e30f, l1 = -1e30f;
#pragma unroll
        for (int e = 0; e < E_NUM; e++) {
            float l = lgs[tid * 8 + e];
            if (l > l0) { l1 = l0; i1 = i0; l0 = l; i0 = e; }
            else if (l > l1) { l1 = l; i1 = e; }
        }
        float r = expf(l1 - l0);
        w0f = 1.f / (1.f + r);
        w1f = r * w0f;
        atomicAdd(&scnt[i0], 1);
        atomicAdd(&scnt[i1], 1);
    }
    __syncthreads();
    if (tid < E_NUM) sbase[tid] = atomicAdd(&g_cnt[tid], scnt[tid]);
    __syncthreads();
    if (tid < 64) {
        int p0 = atomicAdd(&soff[i0], 1);
        int gpos0 = sbase[i0] + p0;
        g_ridx[i0 * B_TOK + gpos0] = token;
        g_rwt [i0 * B_TOK + gpos0] = w0f;
        int p1 = atomicAdd(&soff[i1], 1);
        int gpos1 = sbase[i1] + p1;
        g_ridx[i1 * B_TOK + gpos1] = token;
        g_rwt [i1 * B_TOK + gpos1] = w1f;
    }
}

// ---------------------------------------------------------------------------
// Expert compute over routed tokens. Grid (512, E). Early-exit beyond count.
// Dyn smem: A[64*256] + Bf[64*256] + Wt[32*256] = 160 KB.
// ---------------------------------------------------------------------------
#define EXP_SMEM ((64 * 256 * 2 + 32 * 256) * 4)

__global__ __launch_bounds__(256) void expert_kernel(
    const float* __restrict__ x,
    const float* __restrict__ w1, const float* __restrict__ b1,
    const float* __restrict__ g1, const float* __restrict__ be1,
    const float* __restrict__ w2, const float* __restrict__ b2,
    const float* __restrict__ g2, const float* __restrict__ be2,
    const float* __restrict__ w3, const float* __restrict__ b3,
    float* __restrict__ out)
{
    int e = blockIdx.y;
    int n = g_cnt[e];
    int start = blockIdx.x * 64;
    if (start >= n) return;

    extern __shared__ float sm[];
    float* A  = sm;                  // ping
    float* Bf = sm + 64 * 256;       // pong
    float* Wt = sm + 2 * 64 * 256;   // weight staging
    __shared__ int   stok[64];
    __shared__ float sgw[64];

    int tid = threadIdx.x;
    int tc = tid >> 5;
    int jc = tid & 31;

    if (tid < 64) {
        int r = start + tid;
        if (r < n) {
            stok[tid] = g_ridx[e * B_TOK + r];
            sgw [tid] = g_rwt [e * B_TOK + r];
        } else {
            stok[tid] = -1;
            sgw [tid] = 0.f;
        }
    }
    __syncthreads();

    // gather x rows into A (float4, coalesced within rows)
    const float4* x4 = (const float4*)x;
    float4* A4 = (float4*)A;
#pragma unroll
    for (int i = 0; i < 16; i++) {
        int idx = tid + i * 256;
        int row = idx >> 6, c = idx & 63;
        int tok = stok[row];
        A4[idx] = (tok >= 0) ? x4[(size_t)tok * 64 + c]
                             : make_float4(0.f, 0.f, 0.f, 0.f);
    }

    const size_t we = (size_t)e * 256 * 256;
    float acc[8][8];

    // layer 1: A -> Bf
    gemm_64x256(A, (const float4*)(w1 + we), Wt, acc, tc, jc, tid);
    bias_ln_relu_store(acc, b1 + e * 256, g1 + e * 256, be1 + e * 256, Bf, tc, jc);

    // layer 2: Bf -> A (x no longer needed)
    gemm_64x256(Bf, (const float4*)(w2 + we), Wt, acc, tc, jc, tid);
    bias_ln_relu_store(acc, b2 + e * 256, g2 + e * 256, be2 + e * 256, A, tc, jc);

    // layer 3: A -> gated atomic accumulate into out
    gemm_64x256(A, (const float4*)(w3 + we), Wt, acc, tc, jc, tid);
    {
        float bj[8];
#pragma unroll
        for (int cc = 0; cc < 8; cc++) bj[cc] = b3[e * 256 + jc * 8 + cc];
#pragma unroll
        for (int tt = 0; tt < 8; tt++) {
            int row = tc * 8 + tt;
            int tok = stok[row];
            if (tok < 0) continue;
            float w = sgw[row];
            float* dst = out + (size_t)tok * 256 + jc * 8;
#pragma unroll
            for (int cc = 0; cc < 8; cc++)
                atomicAdd(dst + cc, (acc[tt][cc] + bj[cc]) * w);
        }
    }
}

// ---------------------------------------------------------------------------
// Launch
// ---------------------------------------------------------------------------
extern "C" void kernel_launch(void* const* d_in, const int* in_sizes, int n_in,
                              void* d_out, int out_size)
{
    (void)in_sizes; (void)n_in;
    const float* x   = (const float*)d_in[0];
    const float* gw1 = (const float*)d_in[1];
    const float* gb1 = (const float*)d_in[2];
    const float* gw2 = (const float*)d_in[3];
    const float* gb2 = (const float*)d_in[4];
    const float* w1  = (const float*)d_in[5];
    const float* b1  = (const float*)d_in[6];
    const float* g1  = (const float*)d_in[7];
    const float* be1 = (const float*)d_in[8];
    const float* w2  = (const float*)d_in[9];
    const float* b2  = (const float*)d_in[10];
    const float* g2  = (const float*)d_in[11];
    const float* be2 = (const float*)d_in[12];
    const float* w3  = (const float*)d_in[13];
    const float* b3  = (const float*)d_in[14];
    float* out = (float*)d_out;

    cudaFuncSetAttribute(gating_kernel,
        cudaFuncAttributeMaxDynamicSharedMemorySize, GATE_SMEM);
    cudaFuncSetAttribute(expert_kernel,
        cudaFuncAttributeMaxDynamicSharedMemorySize, EXP_SMEM);

    zero_cnt_kernel<<<1, 32>>>();
    cudaMemsetAsync(d_out, 0, (size_t)out_size * sizeof(float));
    gating_kernel<<<B_TOK / 64, 256, GATE_SMEM>>>(x, gw1, gb1, gw2, gb2);
    expert_kernel<<<dim3(B_TOK / 64, E_NUM), 256, EXP_SMEM>>>(
        x, w1, b1, g1, be1, w2, b2, g2, be2, w3, b3, out);
}